// round 2
// baseline (speedup 1.0000x reference)
#include <cuda_runtime.h>
#include <math.h>

// Problem constants
#define BATCH 2
#define SEQ   2048
#define DIM   1024
#define HEADS 16
#define HSZ   64
#define FFDIM 16384
#define MROWS (BATCH * SEQ)   // 4096

// ---------------------------------------------------------------------------
// Scratch (device globals; no allocation allowed)
// ---------------------------------------------------------------------------
__device__ float g_qkv [(size_t)MROWS * 3 * DIM];   // 48 MB
__device__ float g_att [(size_t)MROWS * DIM];       // 16 MB
__device__ float g_res1[(size_t)MROWS * DIM];       // 16 MB
__device__ float g_ln1 [(size_t)MROWS * DIM];       // 16 MB
__device__ float g_ffh [(size_t)MROWS * FFDIM];     // 256 MB
__device__ float g_res2[(size_t)MROWS * DIM];       // 16 MB

// ---------------------------------------------------------------------------
// SGEMM: C = A[M,K] @ B[K,N] + bias (+ optional ReLU, + optional residual)
// 128x128 tile, BK=8, 256 threads, 8x8 micro-tile per thread.
// ---------------------------------------------------------------------------
template <bool RELU, bool RES>
__global__ __launch_bounds__(256)
void sgemm_kernel(const float* __restrict__ A, const float* __restrict__ B,
                  const float* __restrict__ bias, const float* __restrict__ res,
                  float* __restrict__ C, int M, int N, int K)
{
    __shared__ float As[8][128];
    __shared__ float Bs[8][128];

    const int tid = threadIdx.x;
    const int bm = blockIdx.y * 128;
    const int bn = blockIdx.x * 128;

    // A tile loads: 128 rows x 8 cols -> 256 float4 (one per thread)
    const int arow = tid >> 1;            // 0..127
    const int acol = (tid & 1) * 4;       // 0 or 4
    // B tile loads: 8 rows x 128 cols -> 256 float4
    const int brow = tid >> 5;            // 0..7
    const int bcol = (tid & 31) * 4;      // 0..124

    const int tx = tid & 15;              // micro-tile col group
    const int ty = tid >> 4;              // micro-tile row group

    const float* Aptr = A + (size_t)(bm + arow) * K + acol;
    const float* Bptr = B + (size_t)brow * N + bn + bcol;

    float acc[8][8];
    #pragma unroll
    for (int i = 0; i < 8; i++)
        #pragma unroll
        for (int j = 0; j < 8; j++) acc[i][j] = 0.f;

    for (int k0 = 0; k0 < K; k0 += 8) {
        float4 av = *(const float4*)(Aptr + k0);
        float4 bv = *(const float4*)(Bptr + (size_t)k0 * N);
        As[acol + 0][arow] = av.x;
        As[acol + 1][arow] = av.y;
        As[acol + 2][arow] = av.z;
        As[acol + 3][arow] = av.w;
        *(float4*)&Bs[brow][bcol] = bv;
        __syncthreads();

        #pragma unroll
        for (int k = 0; k < 8; k++) {
            float ar[8], br[8];
            *(float4*)&ar[0] = *(const float4*)&As[k][ty * 8];
            *(float4*)&ar[4] = *(const float4*)&As[k][ty * 8 + 4];
            *(float4*)&br[0] = *(const float4*)&Bs[k][tx * 8];
            *(float4*)&br[4] = *(const float4*)&Bs[k][tx * 8 + 4];
            #pragma unroll
            for (int i = 0; i < 8; i++)
                #pragma unroll
                for (int j = 0; j < 8; j++)
                    acc[i][j] = fmaf(ar[i], br[j], acc[i][j]);
        }
        __syncthreads();
    }

    // Epilogue
    const int ccol = bn + tx * 8;
    float bb[8];
    *(float4*)&bb[0] = *(const float4*)(bias + ccol);
    *(float4*)&bb[4] = *(const float4*)(bias + ccol + 4);

    #pragma unroll
    for (int i = 0; i < 8; i++) {
        const int row = bm + ty * 8 + i;
        float* Crow = C + (size_t)row * N + ccol;
        float v[8];
        #pragma unroll
        for (int j = 0; j < 8; j++) {
            float t = acc[i][j] + bb[j];
            if (RELU) t = fmaxf(t, 0.f);
            v[j] = t;
        }
        if (RES) {
            const float* Rrow = res + (size_t)row * N + ccol;
            float r[8];
            *(float4*)&r[0] = *(const float4*)(Rrow);
            *(float4*)&r[4] = *(const float4*)(Rrow + 4);
            #pragma unroll
            for (int j = 0; j < 8; j++) v[j] += r[j];
        }
        *(float4*)(Crow)     = make_float4(v[0], v[1], v[2], v[3]);
        *(float4*)(Crow + 4) = make_float4(v[4], v[5], v[6], v[7]);
    }
}

// ---------------------------------------------------------------------------
// Causal flash attention, fp32. One block per (query-tile, b*H+h).
// BM=BN=64, HS=64. 256 threads as 16x16, 4x4 micro-tiles.
// qkv layout: [B*T, 3*DIM], q at col 0, k at col DIM, v at col 2*DIM.
// Output y: [B*T, DIM] with d = h*64+hs.
// Static smem only (48 KB exactly): Qs + KVs + Ps, all 64x64 unpadded.
// K is stored TRANSPOSED (KT[hs][key]) so both the S-loop and PV-loop read
// KVs[k*64 + c] contiguously (conflict-free).
// ---------------------------------------------------------------------------
__global__ __launch_bounds__(256)
void attn_kernel(const float* __restrict__ qkv, float* __restrict__ y)
{
    __shared__ float Qs [64 * 64];   // Q[row][hs]
    __shared__ float KVs[64 * 64];   // KT[hs][key] then V[key][hs]
    __shared__ float Ps [64 * 64];   // P[row][key]

    const int qt  = blockIdx.x;         // 0..31 query tile
    const int bh  = blockIdx.y;         // 0..31
    const int b   = bh >> 4;
    const int h   = bh & 15;
    const int tid = threadIdx.x;
    const int tx  = tid & 15;
    const int ty  = tid >> 4;
    const int r0  = ty * 4;             // query rows within tile
    const int c0  = tx * 4;             // key cols / hs cols within tile

    const float* base = qkv + (size_t)b * SEQ * (3 * DIM) + h * HSZ;

    // Load Q tile (64x64), row-major
    for (int i = tid; i < 1024; i += 256) {
        int r = i >> 4, c4 = (i & 15) << 2;
        *(float4*)&Qs[r * 64 + c4] =
            *(const float4*)(base + (size_t)(qt * 64 + r) * (3 * DIM) + c4);
    }

    float o[4][4];
    #pragma unroll
    for (int i = 0; i < 4; i++)
        #pragma unroll
        for (int j = 0; j < 4; j++) o[i][j] = 0.f;
    float mi[4] = {-1e30f, -1e30f, -1e30f, -1e30f};
    float li[4] = {0.f, 0.f, 0.f, 0.f};

    for (int jt = 0; jt <= qt; jt++) {
        __syncthreads();   // prior KVs/Ps consumers done (and Q load on iter 0)
        // Load K tile TRANSPOSED: KT[hs=c][key=r]
        for (int i = tid; i < 1024; i += 256) {
            int r = i >> 4, c4 = (i & 15) << 2;
            float4 kv = *(const float4*)
                (base + (size_t)(jt * 64 + r) * (3 * DIM) + DIM + c4);
            KVs[(c4 + 0) * 64 + r] = kv.x;
            KVs[(c4 + 1) * 64 + r] = kv.y;
            KVs[(c4 + 2) * 64 + r] = kv.z;
            KVs[(c4 + 3) * 64 + r] = kv.w;
        }
        __syncthreads();

        // S = Q @ K^T   (read KT rows contiguously)
        float s[4][4];
        #pragma unroll
        for (int i = 0; i < 4; i++)
            #pragma unroll
            for (int j = 0; j < 4; j++) s[i][j] = 0.f;
        #pragma unroll 8
        for (int k = 0; k < 64; k++) {
            float a[4], bb[4];
            #pragma unroll
            for (int i = 0; i < 4; i++) a[i] = Qs[(r0 + i) * 64 + k];
            *(float4*)&bb[0] = *(const float4*)&KVs[k * 64 + c0];
            #pragma unroll
            for (int i = 0; i < 4; i++)
                #pragma unroll
                for (int j = 0; j < 4; j++)
                    s[i][j] = fmaf(a[i], bb[j], s[i][j]);
        }

        // Scale + causal mask (only needed on diagonal tile)
        #pragma unroll
        for (int i = 0; i < 4; i++)
            #pragma unroll
            for (int j = 0; j < 4; j++) s[i][j] *= 0.125f;
        if (jt == qt) {
            #pragma unroll
            for (int i = 0; i < 4; i++)
                #pragma unroll
                for (int j = 0; j < 4; j++)
                    if (c0 + j > r0 + i) s[i][j] = -1e30f;
        }

        // Online softmax (per-row state replicated across the 16 tx threads)
        #pragma unroll
        for (int i = 0; i < 4; i++) {
            float m = fmaxf(fmaxf(s[i][0], s[i][1]), fmaxf(s[i][2], s[i][3]));
            #pragma unroll
            for (int w = 1; w < 16; w <<= 1)
                m = fmaxf(m, __shfl_xor_sync(0xffffffffu, m, w));
            float mn  = fmaxf(mi[i], m);
            float fac = __expf(mi[i] - mn);
            mi[i] = mn;
            float sum = 0.f;
            #pragma unroll
            for (int j = 0; j < 4; j++) {
                s[i][j] = __expf(s[i][j] - mn);
                sum += s[i][j];
            }
            #pragma unroll
            for (int w = 1; w < 16; w <<= 1)
                sum += __shfl_xor_sync(0xffffffffu, sum, w);
            li[i] = li[i] * fac + sum;
            #pragma unroll
            for (int j = 0; j < 4; j++) o[i][j] *= fac;
        }

        __syncthreads();   // all reads of KVs(K) complete
        // Write P, load V tile row-major (overwrites KVs)
        #pragma unroll
        for (int i = 0; i < 4; i++)
            *(float4*)&Ps[(r0 + i) * 64 + c0] =
                make_float4(s[i][0], s[i][1], s[i][2], s[i][3]);
        for (int i = tid; i < 1024; i += 256) {
            int r = i >> 4, c4 = (i & 15) << 2;
            *(float4*)&KVs[r * 64 + c4] =
                *(const float4*)(base + (size_t)(jt * 64 + r) * (3 * DIM) + 2 * DIM + c4);
        }
        __syncthreads();

        // O += P @ V   (read V rows contiguously)
        #pragma unroll 8
        for (int k = 0; k < 64; k++) {
            float a[4], bb[4];
            #pragma unroll
            for (int i = 0; i < 4; i++) a[i] = Ps[(r0 + i) * 64 + k];
            *(float4*)&bb[0] = *(const float4*)&KVs[k * 64 + c0];
            #pragma unroll
            for (int i = 0; i < 4; i++)
                #pragma unroll
                for (int j = 0; j < 4; j++)
                    o[i][j] = fmaf(a[i], bb[j], o[i][j]);
        }
    }

    // Normalize and store
    #pragma unroll
    for (int i = 0; i < 4; i++) {
        float inv = 1.f / li[i];
        *(float4*)(y + (size_t)(b * SEQ + qt * 64 + r0 + i) * DIM + h * HSZ + c0) =
            make_float4(o[i][0] * inv, o[i][1] * inv, o[i][2] * inv, o[i][3] * inv);
    }
}

// ---------------------------------------------------------------------------
// LayerNorm over last dim (1024). One block per row, 256 threads x 4 elems.
// ---------------------------------------------------------------------------
__global__ __launch_bounds__(256)
void layernorm_kernel(const float* __restrict__ in, const float* __restrict__ g,
                      const float* __restrict__ beta, float* __restrict__ out)
{
    const int row = blockIdx.x;
    const int tid = threadIdx.x;
    const float* xr = in + (size_t)row * DIM;

    float4 v = *(const float4*)(xr + tid * 4);
    float s  = v.x + v.y + v.z + v.w;
    float s2 = v.x * v.x + v.y * v.y + v.z * v.z + v.w * v.w;
    #pragma unroll
    for (int w = 16; w > 0; w >>= 1) {
        s  += __shfl_xor_sync(0xffffffffu, s,  w);
        s2 += __shfl_xor_sync(0xffffffffu, s2, w);
    }
    __shared__ float ss[8], ss2[8];
    if ((tid & 31) == 0) { ss[tid >> 5] = s; ss2[tid >> 5] = s2; }
    __syncthreads();
    float ts = 0.f, ts2 = 0.f;
    #pragma unroll
    for (int i = 0; i < 8; i++) { ts += ss[i]; ts2 += ss2[i]; }

    const float mean = ts * (1.f / DIM);
    const float var  = ts2 * (1.f / DIM) - mean * mean;
    const float inv  = rsqrtf(var + 1e-5f);

    float4 gv = *(const float4*)(g + tid * 4);
    float4 bv = *(const float4*)(beta + tid * 4);
    float4 r;
    r.x = (v.x - mean) * inv * gv.x + bv.x;
    r.y = (v.y - mean) * inv * gv.y + bv.y;
    r.z = (v.z - mean) * inv * gv.z + bv.z;
    r.w = (v.w - mean) * inv * gv.w + bv.w;
    *(float4*)(out + (size_t)row * DIM + tid * 4) = r;
}

// ---------------------------------------------------------------------------
// Launch pipeline (launches only; symbol lookups are capture-safe)
// ---------------------------------------------------------------------------
extern "C" void kernel_launch(void* const* d_in, const int* in_sizes, int n_in,
                              void* d_out, int out_size)
{
    const float* x     = (const float*)d_in[0];
    const float* w_qkv = (const float*)d_in[1];
    const float* b_qkv = (const float*)d_in[2];
    const float* w_fc  = (const float*)d_in[3];
    const float* b_fc  = (const float*)d_in[4];
    const float* g1    = (const float*)d_in[5];
    const float* beta1 = (const float*)d_in[6];
    const float* w_ff1 = (const float*)d_in[7];
    const float* b_ff1 = (const float*)d_in[8];
    const float* w_ff2 = (const float*)d_in[9];
    const float* b_ff2 = (const float*)d_in[10];
    const float* g2    = (const float*)d_in[11];
    const float* beta2 = (const float*)d_in[12];
    float* out = (float*)d_out;

    float *qkv, *att, *res1, *ln1, *ffh, *res2;
    cudaGetSymbolAddress((void**)&qkv,  g_qkv);
    cudaGetSymbolAddress((void**)&att,  g_att);
    cudaGetSymbolAddress((void**)&res1, g_res1);
    cudaGetSymbolAddress((void**)&ln1,  g_ln1);
    cudaGetSymbolAddress((void**)&ffh,  g_ffh);
    cudaGetSymbolAddress((void**)&res2, g_res2);

    // 1) QKV projection: [4096,1024] @ [1024,3072]
    sgemm_kernel<false, false>
        <<<dim3(3 * DIM / 128, MROWS / 128), 256>>>(
            x, w_qkv, b_qkv, nullptr, qkv, MROWS, 3 * DIM, DIM);

    // 2) Causal attention
    attn_kernel<<<dim3(SEQ / 64, BATCH * HEADS), 256>>>(qkv, att);

    // 3) Output projection + residual(x)
    sgemm_kernel<false, true>
        <<<dim3(DIM / 128, MROWS / 128), 256>>>(
            att, w_fc, b_fc, x, res1, MROWS, DIM, DIM);

    // 4) LayerNorm 1
    layernorm_kernel<<<MROWS, 256>>>(res1, g1, beta1, ln1);

    // 5) FF1 + ReLU: [4096,1024] @ [1024,16384]
    sgemm_kernel<true, false>
        <<<dim3(FFDIM / 128, MROWS / 128), 256>>>(
            ln1, w_ff1, b_ff1, nullptr, ffh, MROWS, FFDIM, DIM);

    // 6) FF2 + residual(ln1): [4096,16384] @ [16384,1024]
    sgemm_kernel<false, true>
        <<<dim3(DIM / 128, MROWS / 128), 256>>>(
            ffh, w_ff2, b_ff2, ln1, res2, MROWS, DIM, FFDIM);

    // 7) LayerNorm 2 -> output
    layernorm_kernel<<<MROWS, 256>>>(res2, g2, beta2, out);
}

// round 5
// speedup vs baseline: 2.2905x; 2.2905x over previous
#include <cuda_runtime.h>
#include <cuda_bf16.h>
#include <math.h>
#include <cstdint>

// Problem constants
#define BATCH 2
#define SEQ   2048
#define DIM   1024
#define HEADS 16
#define HSZ   64
#define FFDIM 16384
#define MROWS (BATCH * SEQ)   // 4096

typedef __nv_bfloat16 bf16;

// ---------------------------------------------------------------------------
// Scratch (device globals; no allocation allowed)
// ---------------------------------------------------------------------------
__device__ float g_qkv  [(size_t)MROWS * 3 * DIM];     // fp32 for attention
__device__ bf16  g_xh   [(size_t)MROWS * DIM];
__device__ bf16  g_xl   [(size_t)MROWS * DIM];
__device__ bf16  g_wqkvt_h[(size_t)3 * DIM * DIM];     // [3D][D] K-major
__device__ bf16  g_wqkvt_l[(size_t)3 * DIM * DIM];
__device__ bf16  g_wfct_h [(size_t)DIM * DIM];
__device__ bf16  g_wfct_l [(size_t)DIM * DIM];
__device__ bf16  g_wff1t_h[(size_t)FFDIM * DIM];       // [FF][D]
__device__ bf16  g_wff1t_l[(size_t)FFDIM * DIM];
__device__ bf16  g_wff2t_h[(size_t)DIM * FFDIM];       // [D][FF]
__device__ bf16  g_wff2t_l[(size_t)DIM * FFDIM];
__device__ bf16  g_atth [(size_t)MROWS * DIM];
__device__ bf16  g_attl [(size_t)MROWS * DIM];
__device__ float g_res1 [(size_t)MROWS * DIM];
__device__ float g_ln1  [(size_t)MROWS * DIM];
__device__ bf16  g_ln1h [(size_t)MROWS * DIM];
__device__ bf16  g_ln1l [(size_t)MROWS * DIM];
__device__ bf16  g_ffh_h[(size_t)MROWS * FFDIM];       // relu(ff1) hi
__device__ bf16  g_ffh_l[(size_t)MROWS * FFDIM];       // relu(ff1) lo
__device__ float g_res2 [(size_t)MROWS * DIM];

// ---------------------------------------------------------------------------
// helpers (base sm_100 only: ldmatrix / mma.sync / cp.async)
// ---------------------------------------------------------------------------
__device__ __forceinline__ uint32_t smem_u32(const void* p) {
    uint32_t a;
    asm("{ .reg .u64 t; cvta.to.shared.u64 t, %1; cvt.u32.u64 %0, t; }"
        : "=r"(a) : "l"(p));
    return a;
}
#define SWZ128(off) ((off) ^ (((off) >> 3) & 0x70))

__device__ __forceinline__ void cpa16(uint32_t dst, const void* src) {
    asm volatile("cp.async.cg.shared.global [%0], [%1], 16;"
                 :: "r"(dst), "l"(src));
}
#define CP_COMMIT() asm volatile("cp.async.commit_group;" ::: "memory")
#define CP_WAIT1()  asm volatile("cp.async.wait_group 1;" ::: "memory")
#define CP_WAIT0()  asm volatile("cp.async.wait_group 0;" ::: "memory")

__device__ __forceinline__ void ldsm_x4(uint32_t& r0, uint32_t& r1,
                                        uint32_t& r2, uint32_t& r3, uint32_t a) {
    asm volatile("ldmatrix.sync.aligned.m8n8.x4.shared.b16 {%0,%1,%2,%3}, [%4];"
                 : "=r"(r0), "=r"(r1), "=r"(r2), "=r"(r3) : "r"(a));
}
__device__ __forceinline__ void mma16816(float* d, const uint32_t* a,
                                         const uint32_t* b) {
    asm volatile(
        "mma.sync.aligned.m16n8k16.row.col.f32.bf16.bf16.f32 "
        "{%0,%1,%2,%3}, {%4,%5,%6,%7}, {%8,%9}, {%0,%1,%2,%3};"
        : "+f"(d[0]), "+f"(d[1]), "+f"(d[2]), "+f"(d[3])
        : "r"(a[0]), "r"(a[1]), "r"(a[2]), "r"(a[3]), "r"(b[0]), "r"(b[1]));
}

__device__ __forceinline__ void split2(float v, bf16& h, bf16& l) {
    h = __float2bfloat16(v);
    l = __float2bfloat16(v - __bfloat162float(h));
}
__device__ __forceinline__ void store4bf(bf16* p, bf16 a, bf16 b, bf16 c, bf16 d) {
    *(ushort4*)p = make_ushort4(__bfloat16_as_ushort(a), __bfloat16_as_ushort(b),
                                __bfloat16_as_ushort(c), __bfloat16_as_ushort(d));
}

// ---------------------------------------------------------------------------
// Elementwise split:  in fp32 [n] -> hi/lo bf16 [n]
// ---------------------------------------------------------------------------
__global__ __launch_bounds__(256)
void split_kernel(const float* __restrict__ in, bf16* __restrict__ h,
                  bf16* __restrict__ l, int n4)
{
    int i = blockIdx.x * 256 + threadIdx.x;
    if (i >= n4) return;
    float4 v = ((const float4*)in)[i];
    bf16 h0, h1, h2, h3, l0, l1, l2, l3;
    split2(v.x, h0, l0); split2(v.y, h1, l1);
    split2(v.z, h2, l2); split2(v.w, h3, l3);
    store4bf(h + i * 4, h0, h1, h2, h3);
    store4bf(l + i * 4, l0, l1, l2, l3);
}

// ---------------------------------------------------------------------------
// Transpose + split:  in fp32 [R][C]  ->  out hi/lo bf16 [C][R]
// ---------------------------------------------------------------------------
__global__ __launch_bounds__(256)
void transpose_split_kernel(const float* __restrict__ in, bf16* __restrict__ th,
                            bf16* __restrict__ tl, int R, int C)
{
    __shared__ float t[32][33];
    const int bx = blockIdx.x * 32;   // col base
    const int by = blockIdx.y * 32;   // row base
    const int tx = threadIdx.x & 31;
    const int ty = threadIdx.x >> 5;  // 0..7
    #pragma unroll
    for (int k = 0; k < 4; k++)
        t[ty + k * 8][tx] = in[(size_t)(by + ty + k * 8) * C + bx + tx];
    __syncthreads();
    #pragma unroll
    for (int k = 0; k < 4; k++) {
        float v = t[tx][ty + k * 8];
        bf16 h, l; split2(v, h, l);
        th[(size_t)(bx + ty + k * 8) * R + by + tx] = h;
        tl[(size_t)(bx + ty + k * 8) * R + by + tx] = l;
    }
}

// ---------------------------------------------------------------------------
// Split-bf16 tensor-core GEMM via mma.sync (HMMA.16816).
// C[M,N] = A[M,K] @ B[K,N] (+bias, optional relu / residual).
// A: hi/lo bf16 [M][K] row-major. B: hi/lo bf16 [N][K] (K-major rows).
// Block tile 128x128x64, cp.async double-buffered SW128 smem, 8 warps
// with 64x32 warp tiles. Accumulates AhBh + AhBl + AlBh (fp32).
// ---------------------------------------------------------------------------
#define GBUF 65536
#define GSMEM_BYTES (2 * GBUF)
#define AHo 0
#define ALo 16384
#define BHo 32768
#define BLo 49152

template <bool RELU, bool RES, bool EMIT_BF16, bool WRITE_F32>
__global__ __launch_bounds__(256, 1)
void tc_gemm(const bf16* __restrict__ Ah, const bf16* __restrict__ Al,
             const bf16* __restrict__ Bh, const bf16* __restrict__ Bl,
             const float* __restrict__ bias, const float* __restrict__ res,
             float* __restrict__ C, bf16* __restrict__ Ch, bf16* __restrict__ Cl,
             int M, int N, int K)
{
    extern __shared__ char dynsmem[];
    const uint32_t smb = smem_u32(dynsmem);

    const int tid    = threadIdx.x;
    const int wid    = tid >> 5;
    const int lane   = tid & 31;
    const int warp_m = wid >> 2;          // 0..1
    const int warp_n = wid & 3;           // 0..3
    const int bm     = blockIdx.y * 128;
    const int bn     = blockIdx.x * 128;

    // cp.async source indexing: 1024 16B-chunks per 128x64 tile
    const int ldrow = tid >> 3;           // 0..31 base row (x4 iters of 32)
    const int ldq   = tid & 7;            // 16B chunk within 128B row

    float acc[4][4][4];
    #pragma unroll
    for (int mi = 0; mi < 4; mi++)
        #pragma unroll
        for (int ni = 0; ni < 4; ni++)
            #pragma unroll
            for (int e = 0; e < 4; e++) acc[mi][ni][e] = 0.f;

    const int nchunks = K >> 6;

    // ---- issue chunk loads into buffer ----
    auto issue = [&](int c, int buf) {
        const int k0 = c << 6;
        const uint32_t bb = smb + buf * GBUF;
        #pragma unroll
        for (int t = 0; t < 4; t++) {
            const int row = ldrow + t * 32;
            const uint32_t dst = SWZ128((uint32_t)(row * 128 + ldq * 16));
            const size_t sa = (size_t)(bm + row) * K + k0 + ldq * 8;
            const size_t sb = (size_t)(bn + row) * K + k0 + ldq * 8;
            cpa16(bb + AHo + dst, Ah + sa);
            cpa16(bb + ALo + dst, Al + sa);
            cpa16(bb + BHo + dst, Bh + sb);
            cpa16(bb + BLo + dst, Bl + sb);
        }
        CP_COMMIT();
    };

    issue(0, 0);

    const int arow = warp_m * 64 + (lane & 15);
    const int brow = warp_n * 32 + (lane & 15);
    const int hi16 = lane >> 4;           // chunk half selector

    for (int c = 0; c < nchunks; c++) {
        if (c + 1 < nchunks) { issue(c + 1, (c + 1) & 1); CP_WAIT1(); }
        else                 { CP_WAIT0(); }
        __syncthreads();

        const uint32_t bb = smb + (c & 1) * GBUF;
        #pragma unroll
        for (int ks = 0; ks < 4; ks++) {
            const int chunk = ks * 2 + hi16;
            uint32_t ah[4][4], al[4][4], bh[4][2], bl[4][2];
            #pragma unroll
            for (int mi = 0; mi < 4; mi++) {
                const uint32_t off = SWZ128((uint32_t)((arow + mi * 16) * 128 + chunk * 16));
                ldsm_x4(ah[mi][0], ah[mi][1], ah[mi][2], ah[mi][3], bb + AHo + off);
                ldsm_x4(al[mi][0], al[mi][1], al[mi][2], al[mi][3], bb + ALo + off);
            }
            #pragma unroll
            for (int nb = 0; nb < 2; nb++) {
                const uint32_t off = SWZ128((uint32_t)((brow + nb * 16) * 128 + chunk * 16));
                uint32_t r0, r1, r2, r3;
                ldsm_x4(r0, r1, r2, r3, bb + BHo + off);
                bh[nb * 2][0] = r0; bh[nb * 2][1] = r2;
                bh[nb * 2 + 1][0] = r1; bh[nb * 2 + 1][1] = r3;
                ldsm_x4(r0, r1, r2, r3, bb + BLo + off);
                bl[nb * 2][0] = r0; bl[nb * 2][1] = r2;
                bl[nb * 2 + 1][0] = r1; bl[nb * 2 + 1][1] = r3;
            }
            #pragma unroll
            for (int mi = 0; mi < 4; mi++)
                #pragma unroll
                for (int ni = 0; ni < 4; ni++) {
                    mma16816(acc[mi][ni], ah[mi], bh[ni]);
                    mma16816(acc[mi][ni], ah[mi], bl[ni]);
                    mma16816(acc[mi][ni], al[mi], bh[ni]);
                }
        }
        __syncthreads();
    }

    // ---------------- epilogue (register -> global) ----------------
    const int rb = bm + warp_m * 64 + (lane >> 2);
    const int cb = bn + warp_n * 32 + (lane & 3) * 2;
    #pragma unroll
    for (int mi = 0; mi < 4; mi++) {
        #pragma unroll
        for (int ni = 0; ni < 4; ni++) {
            const int ccol = cb + ni * 8;
            const float b0 = bias[ccol], b1 = bias[ccol + 1];
            #pragma unroll
            for (int half = 0; half < 2; half++) {
                const int row = rb + mi * 16 + half * 8;
                float v0 = acc[mi][ni][half * 2 + 0] + b0;
                float v1 = acc[mi][ni][half * 2 + 1] + b1;
                if (RELU) { v0 = fmaxf(v0, 0.f); v1 = fmaxf(v1, 0.f); }
                if (RES) {
                    const float2 r = *(const float2*)(res + (size_t)row * N + ccol);
                    v0 += r.x; v1 += r.y;
                }
                if (WRITE_F32)
                    *(float2*)(C + (size_t)row * N + ccol) = make_float2(v0, v1);
                if (EMIT_BF16) {
                    bf16 h0, h1, l0, l1;
                    split2(v0, h0, l0); split2(v1, h1, l1);
                    *(ushort2*)(Ch + (size_t)row * N + ccol) =
                        make_ushort2(__bfloat16_as_ushort(h0), __bfloat16_as_ushort(h1));
                    *(ushort2*)(Cl + (size_t)row * N + ccol) =
                        make_ushort2(__bfloat16_as_ushort(l0), __bfloat16_as_ushort(l1));
                }
            }
        }
    }
}

// ---------------------------------------------------------------------------
// Causal flash attention, fp32; emits hi/lo bf16 output.
// ---------------------------------------------------------------------------
__global__ __launch_bounds__(256)
void attn_kernel(const float* __restrict__ qkv, bf16* __restrict__ yh,
                 bf16* __restrict__ yl)
{
    __shared__ float Qs [64 * 64];
    __shared__ float KVs[64 * 64];
    __shared__ float Ps [64 * 64];

    const int qt  = blockIdx.x;
    const int bh  = blockIdx.y;
    const int b   = bh >> 4;
    const int h   = bh & 15;
    const int tid = threadIdx.x;
    const int tx  = tid & 15;
    const int ty  = tid >> 4;
    const int r0  = ty * 4;
    const int c0  = tx * 4;

    const float* base = qkv + (size_t)b * SEQ * (3 * DIM) + h * HSZ;

    for (int i = tid; i < 1024; i += 256) {
        int r = i >> 4, c4 = (i & 15) << 2;
        *(float4*)&Qs[r * 64 + c4] =
            *(const float4*)(base + (size_t)(qt * 64 + r) * (3 * DIM) + c4);
    }

    float o[4][4];
    #pragma unroll
    for (int i = 0; i < 4; i++)
        #pragma unroll
        for (int j = 0; j < 4; j++) o[i][j] = 0.f;
    float mi[4] = {-1e30f, -1e30f, -1e30f, -1e30f};
    float li[4] = {0.f, 0.f, 0.f, 0.f};

    for (int jt = 0; jt <= qt; jt++) {
        __syncthreads();
        for (int i = tid; i < 1024; i += 256) {
            int r = i >> 4, c4 = (i & 15) << 2;
            float4 kv = *(const float4*)
                (base + (size_t)(jt * 64 + r) * (3 * DIM) + DIM + c4);
            KVs[(c4 + 0) * 64 + r] = kv.x;
            KVs[(c4 + 1) * 64 + r] = kv.y;
            KVs[(c4 + 2) * 64 + r] = kv.z;
            KVs[(c4 + 3) * 64 + r] = kv.w;
        }
        __syncthreads();

        float s[4][4];
        #pragma unroll
        for (int i = 0; i < 4; i++)
            #pragma unroll
            for (int j = 0; j < 4; j++) s[i][j] = 0.f;
        #pragma unroll 8
        for (int k = 0; k < 64; k++) {
            float a[4], bb[4];
            #pragma unroll
            for (int i = 0; i < 4; i++) a[i] = Qs[(r0 + i) * 64 + k];
            *(float4*)&bb[0] = *(const float4*)&KVs[k * 64 + c0];
            #pragma unroll
            for (int i = 0; i < 4; i++)
                #pragma unroll
                for (int j = 0; j < 4; j++)
                    s[i][j] = fmaf(a[i], bb[j], s[i][j]);
        }

        #pragma unroll
        for (int i = 0; i < 4; i++)
            #pragma unroll
            for (int j = 0; j < 4; j++) s[i][j] *= 0.125f;
        if (jt == qt) {
            #pragma unroll
            for (int i = 0; i < 4; i++)
                #pragma unroll
                for (int j = 0; j < 4; j++)
                    if (c0 + j > r0 + i) s[i][j] = -1e30f;
        }

        #pragma unroll
        for (int i = 0; i < 4; i++) {
            float m = fmaxf(fmaxf(s[i][0], s[i][1]), fmaxf(s[i][2], s[i][3]));
            #pragma unroll
            for (int w = 1; w < 16; w <<= 1)
                m = fmaxf(m, __shfl_xor_sync(0xffffffffu, m, w));
            float mn  = fmaxf(mi[i], m);
            float fac = __expf(mi[i] - mn);
            mi[i] = mn;
            float sum = 0.f;
            #pragma unroll
            for (int j = 0; j < 4; j++) {
                s[i][j] = __expf(s[i][j] - mn);
                sum += s[i][j];
            }
            #pragma unroll
            for (int w = 1; w < 16; w <<= 1)
                sum += __shfl_xor_sync(0xffffffffu, sum, w);
            li[i] = li[i] * fac + sum;
            #pragma unroll
            for (int j = 0; j < 4; j++) o[i][j] *= fac;
        }

        __syncthreads();
        #pragma unroll
        for (int i = 0; i < 4; i++)
            *(float4*)&Ps[(r0 + i) * 64 + c0] =
                make_float4(s[i][0], s[i][1], s[i][2], s[i][3]);
        for (int i = tid; i < 1024; i += 256) {
            int r = i >> 4, c4 = (i & 15) << 2;
            *(float4*)&KVs[r * 64 + c4] =
                *(const float4*)(base + (size_t)(jt * 64 + r) * (3 * DIM) + 2 * DIM + c4);
        }
        __syncthreads();

        #pragma unroll 8
        for (int k = 0; k < 64; k++) {
            float a[4], bb[4];
            #pragma unroll
            for (int i = 0; i < 4; i++) a[i] = Ps[(r0 + i) * 64 + k];
            *(float4*)&bb[0] = *(const float4*)&KVs[k * 64 + c0];
            #pragma unroll
            for (int i = 0; i < 4; i++)
                #pragma unroll
                for (int j = 0; j < 4; j++)
                    o[i][j] = fmaf(a[i], bb[j], o[i][j]);
        }
    }

    #pragma unroll
    for (int i = 0; i < 4; i++) {
        float inv = 1.f / li[i];
        size_t off = (size_t)(b * SEQ + qt * 64 + r0 + i) * DIM + h * HSZ + c0;
        bf16 h0, h1, h2, h3, l0, l1, l2, l3;
        split2(o[i][0] * inv, h0, l0);
        split2(o[i][1] * inv, h1, l1);
        split2(o[i][2] * inv, h2, l2);
        split2(o[i][3] * inv, h3, l3);
        store4bf(yh + off, h0, h1, h2, h3);
        store4bf(yl + off, l0, l1, l2, l3);
    }
}

// ---------------------------------------------------------------------------
// LayerNorm; optionally also emits hi/lo bf16.
// ---------------------------------------------------------------------------
__global__ __launch_bounds__(256)
void layernorm_kernel(const float* __restrict__ in, const float* __restrict__ g,
                      const float* __restrict__ beta, float* __restrict__ out,
                      bf16* __restrict__ oh, bf16* __restrict__ ol)
{
    const int row = blockIdx.x;
    const int tid = threadIdx.x;
    const float* xr = in + (size_t)row * DIM;

    float4 v = *(const float4*)(xr + tid * 4);
    float s  = v.x + v.y + v.z + v.w;
    float s2 = v.x * v.x + v.y * v.y + v.z * v.z + v.w * v.w;
    #pragma unroll
    for (int w = 16; w > 0; w >>= 1) {
        s  += __shfl_xor_sync(0xffffffffu, s,  w);
        s2 += __shfl_xor_sync(0xffffffffu, s2, w);
    }
    __shared__ float ss[8], ss2[8];
    if ((tid & 31) == 0) { ss[tid >> 5] = s; ss2[tid >> 5] = s2; }
    __syncthreads();
    float ts = 0.f, ts2 = 0.f;
    #pragma unroll
    for (int i = 0; i < 8; i++) { ts += ss[i]; ts2 += ss2[i]; }

    const float mean = ts * (1.f / DIM);
    const float var  = ts2 * (1.f / DIM) - mean * mean;
    const float inv  = rsqrtf(var + 1e-5f);

    float4 gv = *(const float4*)(g + tid * 4);
    float4 bv = *(const float4*)(beta + tid * 4);
    float4 r;
    r.x = (v.x - mean) * inv * gv.x + bv.x;
    r.y = (v.y - mean) * inv * gv.y + bv.y;
    r.z = (v.z - mean) * inv * gv.z + bv.z;
    r.w = (v.w - mean) * inv * gv.w + bv.w;
    *(float4*)(out + (size_t)row * DIM + tid * 4) = r;
    if (oh) {
        bf16 h0, h1, h2, h3, l0, l1, l2, l3;
        split2(r.x, h0, l0); split2(r.y, h1, l1);
        split2(r.z, h2, l2); split2(r.w, h3, l3);
        store4bf(oh + (size_t)row * DIM + tid * 4, h0, h1, h2, h3);
        store4bf(ol + (size_t)row * DIM + tid * 4, l0, l1, l2, l3);
    }
}

// ---------------------------------------------------------------------------
// Launch pipeline
// ---------------------------------------------------------------------------
extern "C" void kernel_launch(void* const* d_in, const int* in_sizes, int n_in,
                              void* d_out, int out_size)
{
    const float* x     = (const float*)d_in[0];
    const float* w_qkv = (const float*)d_in[1];
    const float* b_qkv = (const float*)d_in[2];
    const float* w_fc  = (const float*)d_in[3];
    const float* b_fc  = (const float*)d_in[4];
    const float* g1    = (const float*)d_in[5];
    const float* beta1 = (const float*)d_in[6];
    const float* w_ff1 = (const float*)d_in[7];
    const float* b_ff1 = (const float*)d_in[8];
    const float* w_ff2 = (const float*)d_in[9];
    const float* b_ff2 = (const float*)d_in[10];
    const float* g2    = (const float*)d_in[11];
    const float* beta2 = (const float*)d_in[12];
    float* out = (float*)d_out;

    float *qkv, *res1, *ln1, *res2;
    bf16 *xh, *xl, *wqkvt_h, *wqkvt_l, *wfct_h, *wfct_l;
    bf16 *wff1t_h, *wff1t_l, *wff2t_h, *wff2t_l;
    bf16 *atth, *attl, *ln1h, *ln1l, *ffh_h, *ffh_l;
    cudaGetSymbolAddress((void**)&qkv,     g_qkv);
    cudaGetSymbolAddress((void**)&xh,      g_xh);
    cudaGetSymbolAddress((void**)&xl,      g_xl);
    cudaGetSymbolAddress((void**)&wqkvt_h, g_wqkvt_h);
    cudaGetSymbolAddress((void**)&wqkvt_l, g_wqkvt_l);
    cudaGetSymbolAddress((void**)&wfct_h,  g_wfct_h);
    cudaGetSymbolAddress((void**)&wfct_l,  g_wfct_l);
    cudaGetSymbolAddress((void**)&wff1t_h, g_wff1t_h);
    cudaGetSymbolAddress((void**)&wff1t_l, g_wff1t_l);
    cudaGetSymbolAddress((void**)&wff2t_h, g_wff2t_h);
    cudaGetSymbolAddress((void**)&wff2t_l, g_wff2t_l);
    cudaGetSymbolAddress((void**)&atth,    g_atth);
    cudaGetSymbolAddress((void**)&attl,    g_attl);
    cudaGetSymbolAddress((void**)&res1,    g_res1);
    cudaGetSymbolAddress((void**)&ln1,     g_ln1);
    cudaGetSymbolAddress((void**)&ln1h,    g_ln1h);
    cudaGetSymbolAddress((void**)&ln1l,    g_ln1l);
    cudaGetSymbolAddress((void**)&ffh_h,   g_ffh_h);
    cudaGetSymbolAddress((void**)&ffh_l,   g_ffh_l);
    cudaGetSymbolAddress((void**)&res2,    g_res2);

    cudaFuncSetAttribute(tc_gemm<false, false, false, true>,
                         cudaFuncAttributeMaxDynamicSharedMemorySize, GSMEM_BYTES);
    cudaFuncSetAttribute(tc_gemm<true, false, true, false>,
                         cudaFuncAttributeMaxDynamicSharedMemorySize, GSMEM_BYTES);
    cudaFuncSetAttribute(tc_gemm<false, true, false, true>,
                         cudaFuncAttributeMaxDynamicSharedMemorySize, GSMEM_BYTES);

    // 0) Split inputs / weights into hi/lo bf16 (weights transposed to [N][K])
    split_kernel<<<(MROWS * DIM / 4 + 255) / 256, 256>>>(x, xh, xl, MROWS * DIM / 4);
    transpose_split_kernel<<<dim3(3 * DIM / 32, DIM / 32), 256>>>(w_qkv, wqkvt_h, wqkvt_l, DIM, 3 * DIM);
    transpose_split_kernel<<<dim3(DIM / 32, DIM / 32), 256>>>(w_fc, wfct_h, wfct_l, DIM, DIM);
    transpose_split_kernel<<<dim3(FFDIM / 32, DIM / 32), 256>>>(w_ff1, wff1t_h, wff1t_l, DIM, FFDIM);
    transpose_split_kernel<<<dim3(DIM / 32, FFDIM / 32), 256>>>(w_ff2, wff2t_h, wff2t_l, FFDIM, DIM);

    // 1) QKV projection -> fp32 (for attention)
    tc_gemm<false, false, false, true>
        <<<dim3(3 * DIM / 128, MROWS / 128), 256, GSMEM_BYTES>>>(
            xh, xl, wqkvt_h, wqkvt_l, b_qkv, nullptr, qkv, nullptr, nullptr,
            MROWS, 3 * DIM, DIM);

    // 2) Causal attention -> hi/lo bf16
    attn_kernel<<<dim3(SEQ / 64, BATCH * HEADS), 256>>>(qkv, atth, attl);

    // 3) Output projection + residual(x) -> res1 fp32
    tc_gemm<false, true, false, true>
        <<<dim3(DIM / 128, MROWS / 128), 256, GSMEM_BYTES>>>(
            atth, attl, wfct_h, wfct_l, b_fc, x, res1, nullptr, nullptr,
            MROWS, DIM, DIM);

    // 4) LayerNorm 1 -> ln1 fp32 + hi/lo
    layernorm_kernel<<<MROWS, 256>>>(res1, g1, beta1, ln1, ln1h, ln1l);

    // 5) FF1 + ReLU -> hi/lo bf16 only
    tc_gemm<true, false, true, false>
        <<<dim3(FFDIM / 128, MROWS / 128), 256, GSMEM_BYTES>>>(
            ln1h, ln1l, wff1t_h, wff1t_l, b_ff1, nullptr, nullptr, ffh_h, ffh_l,
            MROWS, FFDIM, DIM);

    // 6) FF2 + residual(ln1) -> res2 fp32
    tc_gemm<false, true, false, true>
        <<<dim3(DIM / 128, MROWS / 128), 256, GSMEM_BYTES>>>(
            ffh_h, ffh_l, wff2t_h, wff2t_l, b_ff2, ln1, res2, nullptr, nullptr,
            MROWS, DIM, FFDIM);

    // 7) LayerNorm 2 -> output
    layernorm_kernel<<<MROWS, 256>>>(res2, g2, beta2, out, nullptr, nullptr);
}